// round 11
// baseline (speedup 1.0000x reference)
#include <cuda_runtime.h>
#include <cstdint>

#define N_NODES 100000
#define N_EDGES 1600000
#define NF 128
#define SCAN_B 1024
#define SCAN_NBLK ((N_NODES + SCAN_B - 1) / SCAN_B)   // 98

// Scratch (__device__ globals only; no allocation anywhere).
__device__ float g_h[(size_t)N_NODES * NF];   // h = x @ W
__device__ int   g_cnt[N_NODES];
__device__ int   g_excl[N_NODES];
__device__ int   g_blksum[SCAN_NBLK];
__device__ int   g_blkoff[SCAN_NBLK];
__device__ int   g_rowptr[N_NODES + 1];
__device__ int   g_cur[N_NODES];
__device__ int   g_esrc[N_EDGES];
__device__ float g_dinv[N_NODES];
__device__ int   g_is64;

// ---------------------------------------------------------------------------
__global__ void detect_idx_kernel(const int* __restrict__ ei32) {
    if (threadIdx.x == 0) {
        int any_odd_nonzero = 0;
        #pragma unroll
        for (int i = 1; i < 64; i += 2)
            if (ei32[i] != 0) any_odd_nonzero = 1;
        g_is64 = any_odd_nonzero ? 0 : 1;
    }
}

__global__ void zero_cnt_kernel() {
    int i = blockIdx.x * blockDim.x + threadIdx.x;
    if (i < N_NODES) g_cnt[i] = 0;
}

__global__ __launch_bounds__(256) void count_deg_kernel(const int* __restrict__ ei32) {
    const int stride = g_is64 ? 2 : 1;
    const long long dstbase = g_is64 ? (2LL * N_EDGES) : (long long)N_EDGES;
    int base = 4 * (blockIdx.x * blockDim.x + threadIdx.x);
    #pragma unroll
    for (int j = 0; j < 4; j++) {
        int e = base + j;
        if (e < N_EDGES)
            atomicAdd(&g_cnt[ei32[dstbase + (long long)stride * e]], 1);
    }
}

__global__ __launch_bounds__(SCAN_B) void scan_a_kernel() {
    __shared__ int sd[SCAN_B];
    const int tid = threadIdx.x;
    const int i = blockIdx.x * SCAN_B + tid;
    int v = (i < N_NODES) ? g_cnt[i] : 0;
    sd[tid] = v;
    __syncthreads();
    #pragma unroll
    for (int off = 1; off < SCAN_B; off <<= 1) {
        int t = (tid >= off) ? sd[tid - off] : 0;
        __syncthreads();
        sd[tid] += t;
        __syncthreads();
    }
    if (i < N_NODES) g_excl[i] = sd[tid] - v;
    if (tid == SCAN_B - 1) g_blksum[blockIdx.x] = sd[tid];
}

__global__ void scan_b_kernel() {
    if (threadIdx.x == 0) {
        int run = 0;
        for (int k = 0; k < SCAN_NBLK; k++) { g_blkoff[k] = run; run += g_blksum[k]; }
    }
}

__global__ void scan_c_kernel() {
    int i = blockIdx.x * blockDim.x + threadIdx.x;
    if (i < N_NODES) {
        int rp = g_excl[i] + g_blkoff[i >> 10];
        g_rowptr[i] = rp;
        g_cur[i] = rp;
        g_dinv[i] = rsqrtf((float)(g_cnt[i] + 1));
        if (i == 0) g_rowptr[N_NODES] = N_EDGES;
    }
}

__global__ __launch_bounds__(256) void place_kernel(const int* __restrict__ ei32) {
    const int stride = g_is64 ? 2 : 1;
    const long long dstbase = g_is64 ? (2LL * N_EDGES) : (long long)N_EDGES;
    int base = 4 * (blockIdx.x * blockDim.x + threadIdx.x);
    #pragma unroll
    for (int j = 0; j < 4; j++) {
        int e = base + j;
        if (e < N_EDGES) {
            int s = ei32[(long long)stride * e];
            int d = ei32[dstbase + (long long)stride * e];
            int slot = atomicAdd(&g_cur[d], 1);
            g_esrc[slot] = s;
        }
    }
}

// ---------------------------------------------------------------------------
// GEMM: g_h = x @ W. Register-tiled f32x2 with PRE-PACKED x in shared:
//   xs2[r][kk] holds {x,x} duplicated pairs -> inner loop has ZERO pack movs.
//   Per kk: 1 LDS.128 (W pair-of-pairs) + 8 broadcast LDS.64 (x pairs)
//           + 16 FMA2  (25 issues / 32 FMAs).
#define BM 64
#define KC 32
__global__ __launch_bounds__(256) void gemm_kernel(
    const float* __restrict__ x, const float* __restrict__ W)
{
    __shared__ float2 xs2[BM][KC];      // row-major: stores conflict-free
    __shared__ float  ws[KC][NF];

    const int tid = threadIdx.x;
    const int tn  = tid & 31;           // col group: cols 4*tn .. 4*tn+3
    const int tm  = tid >> 5;           // row group: rows 8*tm .. 8*tm+7
    const int row0 = blockIdx.x * BM;

    unsigned long long acc[8][2];
    #pragma unroll
    for (int i = 0; i < 8; i++) { acc[i][0] = 0ull; acc[i][1] = 0ull; }

    for (int k0 = 0; k0 < NF; k0 += KC) {
        // stage x chunk as duplicated pairs: 64 rows x 32 k (8 elem/thread)
        #pragma unroll
        for (int t = 0; t < 8; t++) {
            int idx = tid + t * 256;          // 0..2047
            int kk = idx & 31;
            int r  = idx >> 5;
            int rg = row0 + r;
            float v = (rg < N_NODES) ? x[(size_t)rg * NF + k0 + kk] : 0.0f;
            xs2[r][kk] = make_float2(v, v);
        }
        // stage W chunk: 32 k x 128 cols (16 elem/thread)
        #pragma unroll
        for (int t = 0; t < 16; t++) {
            int idx = tid + t * 256;          // 0..4095
            int k = idx >> 7;
            int c = idx & 127;
            ws[k][c] = W[(size_t)(k0 + k) * NF + c];
        }
        __syncthreads();

        #pragma unroll 8
        for (int kk = 0; kk < KC; kk++) {
            const ulonglong2 wv =
                *reinterpret_cast<const ulonglong2*>(&ws[kk][tn * 4]);
            #pragma unroll
            for (int i = 0; i < 8; i++) {
                const unsigned long long x2 =
                    *reinterpret_cast<const unsigned long long*>(&xs2[tm * 8 + i][kk]);
                asm("fma.rn.f32x2 %0, %1, %2, %0;"
                    : "+l"(acc[i][0]) : "l"(x2), "l"(wv.x));
                asm("fma.rn.f32x2 %0, %1, %2, %0;"
                    : "+l"(acc[i][1]) : "l"(x2), "l"(wv.y));
            }
        }
        __syncthreads();
    }

    #pragma unroll
    for (int i = 0; i < 8; i++) {
        const int rg = row0 + tm * 8 + i;
        if (rg < N_NODES) {
            float4 v;
            asm("mov.b64 {%0, %1}, %2;" : "=f"(v.x), "=f"(v.y) : "l"(acc[i][0]));
            asm("mov.b64 {%0, %1}, %2;" : "=f"(v.z), "=f"(v.w) : "l"(acc[i][1]));
            *reinterpret_cast<float4*>(&g_h[(size_t)rg * NF + tn * 4]) = v;
        }
    }
}

// ---------------------------------------------------------------------------
// Gather: one block per dst node, thread = feature column. No atomics.
#define ETILE 128
__global__ __launch_bounds__(128) void gather_kernel(
    const float* __restrict__ b, float* __restrict__ out)
{
    __shared__ int   ss[ETILE];
    __shared__ float sv[ETILE];

    const int d = blockIdx.x;
    const int c = threadIdx.x;
    const int start = g_rowptr[d];
    const int end   = g_rowptr[d + 1];
    const float dinv_d = g_dinv[d];

    float acc = dinv_d * g_h[(size_t)d * NF + c];   // self loop

    for (int t = start; t < end; t += ETILE) {
        const int n = min(ETILE, end - t);
        if (c < n) {
            int s = g_esrc[t + c];
            ss[c] = s;
            sv[c] = g_dinv[s];
        }
        __syncthreads();
        for (int j = 0; j < n; j++) {
            acc = fmaf(g_h[(size_t)ss[j] * NF + c], sv[j], acc);
        }
        __syncthreads();
    }

    out[(size_t)d * NF + c] = b[c] + dinv_d * acc;
}

// ---------------------------------------------------------------------------
extern "C" void kernel_launch(void* const* d_in, const int* in_sizes, int n_in,
                              void* d_out, int out_size) {
    const float* x    = (const float*)d_in[0];
    const int*   ei32 = (const int*)d_in[1];
    const float* W    = (const float*)d_in[2];
    const float* b    = (const float*)d_in[3];
    float*       out  = (float*)d_out;

    detect_idx_kernel<<<1, 32>>>(ei32);
    zero_cnt_kernel<<<(N_NODES + 255) / 256, 256>>>();
    count_deg_kernel<<<(N_EDGES / 4 + 255) / 256, 256>>>(ei32);
    // position 4: ncu capture slot -> profile the GEMM
    gemm_kernel<<<(N_NODES + BM - 1) / BM, 256>>>(x, W);
    scan_a_kernel<<<SCAN_NBLK, SCAN_B>>>();
    scan_b_kernel<<<1, 32>>>();
    scan_c_kernel<<<(N_NODES + 255) / 256, 256>>>();
    place_kernel<<<(N_EDGES / 4 + 255) / 256, 256>>>(ei32);
    gather_kernel<<<N_NODES, 128>>>(b, out);
}

// round 13
// speedup vs baseline: 1.0402x; 1.0402x over previous
#include <cuda_runtime.h>
#include <cstdint>

#define N_NODES 100000
#define N_EDGES 1600000
#define NF 128
#define SCAN_B 1024
#define SCAN_NBLK ((N_NODES + SCAN_B - 1) / SCAN_B)   // 98

// Scratch (__device__ globals only; no allocation anywhere).
__device__ float g_h[(size_t)N_NODES * NF];   // h = x @ W
__device__ int   g_cnt[N_NODES];
__device__ int   g_excl[N_NODES];
__device__ int   g_blksum[SCAN_NBLK];
__device__ int   g_blkoff[SCAN_NBLK];
__device__ int   g_rowptr[N_NODES + 1];
__device__ int   g_cur[N_NODES];
__device__ int   g_esrc[N_EDGES];
__device__ float g_dinv[N_NODES];
__device__ int   g_is64;

// ---------------------------------------------------------------------------
__global__ void detect_idx_kernel(const int* __restrict__ ei32) {
    if (threadIdx.x == 0) {
        int any_odd_nonzero = 0;
        #pragma unroll
        for (int i = 1; i < 64; i += 2)
            if (ei32[i] != 0) any_odd_nonzero = 1;
        g_is64 = any_odd_nonzero ? 0 : 1;
    }
}

__global__ void zero_cnt_kernel() {
    int i = blockIdx.x * blockDim.x + threadIdx.x;
    if (i < N_NODES) g_cnt[i] = 0;
}

__global__ __launch_bounds__(256) void count_deg_kernel(const int* __restrict__ ei32) {
    const int stride = g_is64 ? 2 : 1;
    const long long dstbase = g_is64 ? (2LL * N_EDGES) : (long long)N_EDGES;
    int base = 4 * (blockIdx.x * blockDim.x + threadIdx.x);
    #pragma unroll
    for (int j = 0; j < 4; j++) {
        int e = base + j;
        if (e < N_EDGES)
            atomicAdd(&g_cnt[ei32[dstbase + (long long)stride * e]], 1);
    }
}

__global__ __launch_bounds__(SCAN_B) void scan_a_kernel() {
    __shared__ int sd[SCAN_B];
    const int tid = threadIdx.x;
    const int i = blockIdx.x * SCAN_B + tid;
    int v = (i < N_NODES) ? g_cnt[i] : 0;
    sd[tid] = v;
    __syncthreads();
    #pragma unroll
    for (int off = 1; off < SCAN_B; off <<= 1) {
        int t = (tid >= off) ? sd[tid - off] : 0;
        __syncthreads();
        sd[tid] += t;
        __syncthreads();
    }
    if (i < N_NODES) g_excl[i] = sd[tid] - v;
    if (tid == SCAN_B - 1) g_blksum[blockIdx.x] = sd[tid];
}

__global__ void scan_b_kernel() {
    if (threadIdx.x == 0) {
        int run = 0;
        for (int k = 0; k < SCAN_NBLK; k++) { g_blkoff[k] = run; run += g_blksum[k]; }
    }
}

__global__ void scan_c_kernel() {
    int i = blockIdx.x * blockDim.x + threadIdx.x;
    if (i < N_NODES) {
        int rp = g_excl[i] + g_blkoff[i >> 10];
        g_rowptr[i] = rp;
        g_cur[i] = rp;
        g_dinv[i] = rsqrtf((float)(g_cnt[i] + 1));
        if (i == 0) g_rowptr[N_NODES] = N_EDGES;
    }
}

__global__ __launch_bounds__(256) void place_kernel(const int* __restrict__ ei32) {
    const int stride = g_is64 ? 2 : 1;
    const long long dstbase = g_is64 ? (2LL * N_EDGES) : (long long)N_EDGES;
    int base = 4 * (blockIdx.x * blockDim.x + threadIdx.x);
    #pragma unroll
    for (int j = 0; j < 4; j++) {
        int e = base + j;
        if (e < N_EDGES) {
            int s = ei32[(long long)stride * e];
            int d = ei32[dstbase + (long long)stride * e];
            int slot = atomicAdd(&g_cur[d], 1);
            g_esrc[slot] = s;
        }
    }
}

// ---------------------------------------------------------------------------
// GEMM: g_h = x @ W. EXACT R10 version (87.3us proven).
//   block 256 thr, tile M=64 x N=128, k-chunks of 32.
//   thread tile 8 rows x 4 cols = 16 f32x2 accumulators.
#define BM 64
#define KC 32
__global__ __launch_bounds__(256) void gemm_kernel(
    const float* __restrict__ x, const float* __restrict__ W)
{
    __shared__ float xsT[KC][BM + 1];   // stride 65: conflict-free stores
    __shared__ float ws[KC][NF];

    const int tid = threadIdx.x;
    const int tn  = tid & 31;           // col group: cols 4*tn .. 4*tn+3
    const int tm  = tid >> 5;           // row group: rows 8*tm .. 8*tm+7
    const int row0 = blockIdx.x * BM;

    unsigned long long acc[8][2];
    #pragma unroll
    for (int i = 0; i < 8; i++) { acc[i][0] = 0ull; acc[i][1] = 0ull; }

    for (int k0 = 0; k0 < NF; k0 += KC) {
        #pragma unroll
        for (int t = 0; t < 8; t++) {
            int idx = tid + t * 256;          // 0..2047
            int kk = idx & 31;
            int r  = idx >> 5;
            int rg = row0 + r;
            xsT[kk][r] = (rg < N_NODES) ? x[(size_t)rg * NF + k0 + kk] : 0.0f;
        }
        #pragma unroll
        for (int t = 0; t < 16; t++) {
            int idx = tid + t * 256;          // 0..4095
            int k = idx >> 7;
            int c = idx & 127;
            ws[k][c] = W[(size_t)(k0 + k) * NF + c];
        }
        __syncthreads();

        #pragma unroll 8
        for (int kk = 0; kk < KC; kk++) {
            const ulonglong2 wv =
                *reinterpret_cast<const ulonglong2*>(&ws[kk][tn * 4]);
            #pragma unroll
            for (int i = 0; i < 8; i++) {
                const float xv = xsT[kk][tm * 8 + i];
                unsigned long long x2;
                asm("mov.b64 %0, {%1, %1};" : "=l"(x2) : "f"(xv));
                asm("fma.rn.f32x2 %0, %1, %2, %0;"
                    : "+l"(acc[i][0]) : "l"(x2), "l"(wv.x));
                asm("fma.rn.f32x2 %0, %1, %2, %0;"
                    : "+l"(acc[i][1]) : "l"(x2), "l"(wv.y));
            }
        }
        __syncthreads();
    }

    #pragma unroll
    for (int i = 0; i < 8; i++) {
        const int rg = row0 + tm * 8 + i;
        if (rg < N_NODES) {
            float4 v;
            asm("mov.b64 {%0, %1}, %2;" : "=f"(v.x), "=f"(v.y) : "l"(acc[i][0]));
            asm("mov.b64 {%0, %1}, %2;" : "=f"(v.z), "=f"(v.w) : "l"(acc[i][1]));
            *reinterpret_cast<float4*>(&g_h[(size_t)rg * NF + tn * 4]) = v;
        }
    }
}

// ---------------------------------------------------------------------------
// Gather: one block per dst node, thread = feature column. No atomics.
// 4 independent accumulators -> per-thread MLP=4 on the h[src] L2 loads.
#define ETILE 128
__global__ __launch_bounds__(128) void gather_kernel(
    const float* __restrict__ b, float* __restrict__ out)
{
    __shared__ int   ss[ETILE];
    __shared__ float sv[ETILE];

    const int d = blockIdx.x;
    const int c = threadIdx.x;
    const int start = g_rowptr[d];
    const int end   = g_rowptr[d + 1];
    const float dinv_d = g_dinv[d];

    float a0 = dinv_d * g_h[(size_t)d * NF + c];   // self loop
    float a1 = 0.0f, a2 = 0.0f, a3 = 0.0f;

    for (int t = start; t < end; t += ETILE) {
        const int n = min(ETILE, end - t);
        if (c < n) {
            int s = g_esrc[t + c];
            ss[c] = s;
            sv[c] = g_dinv[s];
        }
        __syncthreads();
        int j = 0;
        for (; j + 4 <= n; j += 4) {
            a0 = fmaf(g_h[(size_t)ss[j + 0] * NF + c], sv[j + 0], a0);
            a1 = fmaf(g_h[(size_t)ss[j + 1] * NF + c], sv[j + 1], a1);
            a2 = fmaf(g_h[(size_t)ss[j + 2] * NF + c], sv[j + 2], a2);
            a3 = fmaf(g_h[(size_t)ss[j + 3] * NF + c], sv[j + 3], a3);
        }
        for (; j < n; j++)
            a0 = fmaf(g_h[(size_t)ss[j] * NF + c], sv[j], a0);
        __syncthreads();
    }

    out[(size_t)d * NF + c] = b[c] + dinv_d * ((a0 + a1) + (a2 + a3));
}

// ---------------------------------------------------------------------------
extern "C" void kernel_launch(void* const* d_in, const int* in_sizes, int n_in,
                              void* d_out, int out_size) {
    const float* x    = (const float*)d_in[0];
    const int*   ei32 = (const int*)d_in[1];
    const float* W    = (const float*)d_in[2];
    const float* b    = (const float*)d_in[3];
    float*       out  = (float*)d_out;

    detect_idx_kernel<<<1, 32>>>(ei32);
    zero_cnt_kernel<<<(N_NODES + 255) / 256, 256>>>();
    count_deg_kernel<<<(N_EDGES / 4 + 255) / 256, 256>>>(ei32);
    // position 4: ncu capture slot -> profile the GEMM
    gemm_kernel<<<(N_NODES + BM - 1) / BM, 256>>>(x, W);
    scan_a_kernel<<<SCAN_NBLK, SCAN_B>>>();
    scan_b_kernel<<<1, 32>>>();
    scan_c_kernel<<<(N_NODES + 255) / 256, 256>>>();
    place_kernel<<<(N_EDGES / 4 + 255) / 256, 256>>>(ei32);
    gather_kernel<<<N_NODES, 128>>>(b, out);
}